// round 4
// baseline (speedup 1.0000x reference)
#include <cuda_runtime.h>
#include <cstdint>

// RandomRoll: out[b,c,h,w] = x[b,c,(h - sh) & 511, (w - sw) & 511]
// x: [64, 3, 512, 512] fp32; shifts: [64, 2] int32.
// R4: one full 512-float row per warp (x2 rows), circular-within-warp:
//   lane loads vecs (v0 + lane + 32k) & 127, k=0..3  -> whole source row in regs
//   realignment via shfl with lane-0 contributing A[k+1] (wrap closes in-warp)
// No neighbor prefetch, all 8 LDG.128 front-batched for ~20KB read payload/SM.

static constexpr int HMASK = 511;
static constexpr int WMASK = 511;
static constexpr int TPB   = 256;
static constexpr unsigned FULL = 0xffffffffu;

// Realign output vec j = lane + 32k from the in-register source row A[0..3].
// off is warp-uniform (0..3). Neighbor of A[k]@lane is A[k]@lane+1, except
// lane 31 which needs A[(k+1)&3]@lane0 -> lane 0 contributes that value.
template<int K>
__device__ __forceinline__ float4 realign(const float4 A[4], int off, int lane)
{
    float4 a = A[K];
    if (off == 0) return a;
    const float4 an = A[(K + 1) & 3];
    int src = (lane + 1) & 31;
    float4 B;
    B.x = __shfl_sync(FULL, (lane == 0) ? an.x : a.x, src);
    B.y = __shfl_sync(FULL, (lane == 0) ? an.y : a.y, src);
    B.z = __shfl_sync(FULL, (lane == 0) ? an.z : a.z, src);
    B.w = __shfl_sync(FULL, (lane == 0) ? an.w : a.w, src);
    if (off == 1) return make_float4(a.y, a.z, a.w, B.x);
    if (off == 2) return make_float4(a.z, a.w, B.x, B.y);
    return make_float4(a.w, B.x, B.y, B.z);
}

__global__ void __launch_bounds__(TPB)
random_roll_rows(const float4* __restrict__ x4,
                 const int*    __restrict__ shifts,
                 float4*       __restrict__ out4,
                 int n_rows)   // rows = (b*3+c)*512 + h, 128 float4 each
{
    int lane = threadIdx.x & 31;
    int warp = blockIdx.x * (TPB / 32) + (threadIdx.x >> 5);
    int r0 = warp * 2;
    if (r0 >= n_rows) return;
    int r1 = r0 + 1;
    bool has1 = (r1 < n_rows);
    int r1s = has1 ? r1 : r0;          // safe row for loads when odd count

    // ---- Row setup (shift loads are broadcast LDG.32, resolve early) ----
    int h0  = r0 & HMASK,  bc0 = r0 >> 9,  b0 = bc0 / 3;
    int h1  = r1s & HMASK, bc1 = r1s >> 9, b1 = bc1 / 3;
    int sh0 = __ldg(&shifts[2 * b0]), sw0 = __ldg(&shifts[2 * b0 + 1]);
    int sh1 = __ldg(&shifts[2 * b1]), sw1 = __ldg(&shifts[2 * b1 + 1]);

    const float4* src0 = x4 + ((size_t)((bc0 << 9) | ((h0 - sh0) & HMASK)) << 7);
    const float4* src1 = x4 + ((size_t)((bc1 << 9) | ((h1 - sh1) & HMASK)) << 7);

    int s00 = (-sw0) & WMASK, off0 = s00 & 3, v00 = s00 >> 2;
    int s01 = (-sw1) & WMASK, off1 = s01 & 3, v01 = s01 >> 2;

    // ---- Phase 1: all 8 aligned LDG.128 back-to-back ----
    float4 A0[4], A1[4];
    #pragma unroll
    for (int k = 0; k < 4; k++) A0[k] = src0[(v00 + lane + 32 * k) & 127];
    #pragma unroll
    for (int k = 0; k < 4; k++) A1[k] = src1[(v01 + lane + 32 * k) & 127];

    // ---- Phase 2: realign + store (aligned STG.128, coalesced per k) ----
    float4* o0 = out4 + ((size_t)r0 << 7) + lane;
    o0[ 0] = realign<0>(A0, off0, lane);
    o0[32] = realign<1>(A0, off0, lane);
    o0[64] = realign<2>(A0, off0, lane);
    o0[96] = realign<3>(A0, off0, lane);

    if (has1) {
        float4* o1 = out4 + ((size_t)r1 << 7) + lane;
        o1[ 0] = realign<0>(A1, off1, lane);
        o1[32] = realign<1>(A1, off1, lane);
        o1[64] = realign<2>(A1, off1, lane);
        o1[96] = realign<3>(A1, off1, lane);
    }
}

// Scalar tail for any floats past the last whole row (defensive; unused here).
__global__ void random_roll_tail(const float* __restrict__ x,
                                 const int*   __restrict__ shifts,
                                 float*       __restrict__ out,
                                 int start, int total)
{
    int i = start + blockIdx.x * blockDim.x + threadIdx.x;
    if (i >= total) return;
    int w   = i & WMASK;
    int row = i >> 9;
    int h   = row & HMASK;
    int bc  = row >> 9;
    int b   = bc / 3;
    int sh = shifts[2 * b];
    int sw = shifts[2 * b + 1];
    out[i] = x[(((size_t)((bc << 9) | ((h - sh) & HMASK))) << 9) + ((w - sw) & WMASK)];
}

extern "C" void kernel_launch(void* const* d_in, const int* in_sizes, int n_in,
                              void* d_out, int out_size)
{
    const float4* x4     = (const float4*)d_in[0];
    const int*    shifts = (const int*)d_in[1];
    float4*       out4   = (float4*)d_out;

    int n_rows = out_size >> 9;                 // whole 512-float rows
    if (n_rows > 0) {
        int warps  = (n_rows + 1) / 2;          // 2 rows per warp
        int blocks = (warps + (TPB / 32) - 1) / (TPB / 32);
        random_roll_rows<<<blocks, TPB>>>(x4, shifts, out4, n_rows);
    }
    int tail_start = n_rows << 9;
    int tail = out_size - tail_start;
    if (tail > 0) {
        random_roll_tail<<<(tail + 255) / 256, 256>>>((const float*)d_in[0], shifts,
                                                      (float*)d_out, tail_start, out_size);
    }
}